// round 17
// baseline (speedup 1.0000x reference)
#include <cuda_runtime.h>
#include <math.h>

#define EPSF 1e-4f
typedef unsigned long long u64;

__device__ __forceinline__ u64 pack2(float x){
  u64 r; unsigned xi = __float_as_uint(x);
  asm("mov.b64 %0, {%1, %1};" : "=l"(r) : "r"(xi));
  return r;
}
__device__ __forceinline__ void fma2(u64 &acc, u64 a, u64 b){
  asm("fma.rn.f32x2 %0, %1, %2, %0;" : "+l"(acc) : "l"(a), "l"(b));
}
__device__ __forceinline__ float2 unpack2(u64 v){
  unsigned lo, hi;
  asm("mov.b64 {%0, %1}, %2;" : "=r"(lo), "=r"(hi) : "l"(v));
  return make_float2(__uint_as_float(lo), __uint_as_float(hi));
}
__device__ __forceinline__ float rsum32(float v){
  #pragma unroll
  for (int o=16;o;o>>=1) v += __shfl_xor_sync(0xffffffffu, v, o);
  return v;
}
__device__ __forceinline__ float rsum16(float v){
  #pragma unroll
  for (int o=8;o;o>>=1) v += __shfl_xor_sync(0xffffffffu, v, o);
  return v;
}
__device__ __forceinline__ float rmax16(float v){
  #pragma unroll
  for (int o=8;o;o>>=1) v = fmaxf(v, __shfl_xor_sync(0xffffffffu, v, o));
  return v;
}
__device__ __forceinline__ float sigm(float x){ return 1.f/(1.f+expf(-x)); }
__device__ __forceinline__ float splus(float x){ return fmaxf(x,0.f)+log1pf(expf(-fabsf(x))); }

struct Smem {
  float w1s[260][128];   // 130KB staged w1
  float w2s[128][128];   // 64KB staged w2
  float sci[260];
  float sh1[128];
  float sct[128];
  float sc[16][132];
  float smix[16][16];
  float satt[128];
  float sbuf[16][128];
  float ssp[16], smaM[16], sal[16], sgs[16];
  float ssq[16], sms[16], smm[16];
  float sraw[4][16];
  float sred[4][3];
  float snv, srl, sval;
  int   sidx;
};

__global__ void __launch_bounds__(512,1) cfrm_kernel(
   const int* __restrict__ tokens, const float* __restrict__ emb,
   const float* __restrict__ ln_g, const float* __restrict__ ln_b,
   const float* __restrict__ w1, const float* __restrict__ b1,
   const float* __restrict__ w2, const float* __restrict__ b2,
   const float* __restrict__ gate_w, const float* __restrict__ gate_b,
   const float* __restrict__ assign_w, const float* __restrict__ assign_b,
   const float* __restrict__ nov_w, const float* __restrict__ nov_b,
   const float* __restrict__ relax_w, const float* __restrict__ relax_b,
   const float* __restrict__ cc_w, const float* __restrict__ cc_b,
   const float* __restrict__ cs_w, const float* __restrict__ cs_b,
   const float* __restrict__ md_w, const float* __restrict__ md_b,
   const float* __restrict__ att_w, const float* __restrict__ att_b,
   const float* __restrict__ cw1, const float* __restrict__ cb1,
   const float* __restrict__ cw2, const float* __restrict__ cb2,
   float* __restrict__ out)
{
  extern __shared__ __align__(128) char smem_raw[];
  Smem* S = (Smem*)smem_raw;

  const int tid  = threadIdx.x;
  const int ht   = tid & 127;
  const int lane = tid & 31;
  const int wid  = tid >> 5;
  const int b    = blockIdx.x;

  const int j4  = tid & 31;
  const int isl = tid >> 5;

  // ---- prologue: stage w1, w2 into smem; init state ----
  {
    const float4* src1 = (const float4*)w1;
    float4* dst1 = (float4*)S->w1s;
    for (int i = tid; i < 260*32; i += 512) dst1[i] = src1[i];
    const float4* src2 = (const float4*)w2;
    float4* dst2 = (float4*)S->w2s;
    for (int i = tid; i < 128*32; i += 512) dst2[i] = src2[i];
  }
  for (int i = tid; i < 16*132; i += 512) ((float*)S->sc)[i] = 0.f;
  if (tid < 16){ S->ssp[tid] = 1.f; S->smaM[tid] = 0.f; }

  // first token/emb prefetch (before barrier; overlaps staging)
  int tok_cur = 0; float e_cur = 0.f;
  if (tid < 128){
    tok_cur = tokens[b*512];
    e_cur = emb[tok_cur*128 + tid];
  }
  __syncthreads();

  int tok_nxt = 0; float e_nxt = 0.f;

  for (int t = 0; t < 512; t++){
    if (tid < 128){
      if (tid == 0) S->sval = (tok_cur != 0) ? 1.f : 0.f;
      float ps = rsum32(e_cur);
      float pq = rsum32(e_cur*e_cur);
      if (lane == 0){ S->sred[wid][0] = ps; S->sred[wid][1] = pq; }
    }
    if (wid == 8){
      const int c = lane & 15;
      float sp = S->ssp[c];
      float m  = S->smaM[c];
      float score = m + logf(1.f/(sp+EPSF)+EPSF);
      float mx = rmax16(score);
      float ex = expf(score - mx);
      float sm = rsum16(ex);
      float a  = ex / sm;
      S->sal[c] = a;
      float u   = rsum16(a*sp);
      float ent = rsum16(-a*logf(fmaxf(a,1e-8f)));
      float mm2 = rmax16(m);
      float en  = mm2 + logf(rsum16(expf(m - mm2)));
      if (lane == 0){ S->sci[256] = u; S->sci[258] = en; S->sci[259] = ent; }
    }
    __syncthreads(); // S1
    if (tid < 128){
      float mu = (S->sred[0][0]+S->sred[1][0]+S->sred[2][0]+S->sred[3][0]) * (1.f/128.f);
      float mq = (S->sred[0][1]+S->sred[1][1]+S->sred[2][1]+S->sred[3][1]) * (1.f/128.f);
      float var = mq - mu*mu;
      float te = (e_cur - mu) * rsqrtf(var + 1e-5f) * ln_g[tid] + ln_b[tid];
      S->sci[tid] = te;
      float core = 0.f;
      #pragma unroll
      for (int c = 0; c < 16; c++) core += S->sal[c] * S->sc[c][tid];
      S->sci[128+tid] = core;
      float dv = 0.f;
      #pragma unroll
      for (int c = 0; c < 16; c++){ float dd = S->sc[c][tid] - core; dv += S->sal[c]*dd*dd; }
      dv = rsum32(dv);
      if (lane == 0) S->sred[wid][2] = dv;
    }
    __syncthreads(); // S2

    // ---- w1 [260,128] from smem ----
    {
      u64 ax = 0, ay = 0;
      const int lo = isl * 16;
      #pragma unroll
      for (int r = 0; r < 16; r++){
        const int i = lo + r;
        ulonglong2 w = *(const ulonglong2*)&S->w1s[i][j4*4];
        u64 p0 = pack2(S->sci[i]);
        fma2(ax, p0, w.x); fma2(ay, p0, w.y);
      }
      if (isl < 4){
        const int i = 256 + isl;
        ulonglong2 w = *(const ulonglong2*)&S->w1s[i][j4*4];
        float xv;
        if (isl == 1)
          xv = (S->sred[0][2]+S->sred[1][2]+S->sred[2][2]+S->sred[3][2]) * (1.f/128.f);
        else
          xv = S->sci[i];
        u64 p0 = pack2(xv);
        fma2(ax, p0, w.x); fma2(ay, p0, w.y);
      }
      float2 l = unpack2(ax), h2 = unpack2(ay);
      *(float4*)&S->sbuf[isl][j4*4] = make_float4(l.x, l.y, h2.x, h2.y);
    }
    __syncthreads(); // S3
    if (tid < 128){
      float s = b1[tid];
      #pragma unroll
      for (int k = 0; k < 16; k++) s += S->sbuf[k][tid];
      S->sh1[tid] = tanhf(s);
    }
    __syncthreads(); // S4

    // ---- w2 [128,128] from smem ----
    {
      u64 ax = 0, ay = 0;
      const int lo = isl * 8;
      #pragma unroll
      for (int r = 0; r < 8; r++){
        const int i = lo + r;
        ulonglong2 w = *(const ulonglong2*)&S->w2s[i][j4*4];
        u64 p0 = pack2(S->sh1[i]);
        fma2(ax, p0, w.x); fma2(ay, p0, w.y);
      }
      float2 l = unpack2(ax), h2 = unpack2(ay);
      *(float4*)&S->sbuf[isl][j4*4] = make_float4(l.x, l.y, h2.x, h2.y);
    }
    __syncthreads(); // S5
    if (tid < 128){
      float s = b2[tid];
      #pragma unroll
      for (int k = 0; k < 16; k++) s += S->sbuf[k][tid];
      S->sct[tid] = tanhf(s);
    }
    __syncthreads(); // S6

    // ---- prefetch next token/emb (hidden under heads/cc) ----
    if (tid < 128 && t < 511){
      tok_nxt = tokens[b*512 + t + 1];
      e_nxt = emb[tok_nxt*128 + tid];
    }

    // ---- small heads: cooperative 512-thread matvec ----
    {
      const int head = wid >> 2;
      const int c4o  = (wid & 3) * 4;
      const float* W = (head==0)? gate_w : (head==1)? assign_w : (head==2)? cs_w : md_w;
      float4 a0 = {0,0,0,0};
      #pragma unroll
      for (int r = 0; r < 4; r++){
        const int i = lane*4 + r;
        float4 w4 = *(const float4*)&W[i*16 + c4o];
        float xv = S->sct[i];
        a0.x += xv*w4.x; a0.y += xv*w4.y; a0.z += xv*w4.z; a0.w += xv*w4.w;
      }
      #pragma unroll
      for (int o = 16; o; o >>= 1){
        a0.x += __shfl_xor_sync(0xffffffffu, a0.x, o);
        a0.y += __shfl_xor_sync(0xffffffffu, a0.y, o);
        a0.z += __shfl_xor_sync(0xffffffffu, a0.z, o);
        a0.w += __shfl_xor_sync(0xffffffffu, a0.w, o);
      }
      if (lane == 0){
        const float* Bp = (head==0)? gate_b : (head==1)? assign_b : (head==2)? cs_b : md_b;
        S->sraw[head][c4o+0] = a0.x + Bp[c4o+0];
        S->sraw[head][c4o+1] = a0.y + Bp[c4o+1];
        S->sraw[head][c4o+2] = a0.z + Bp[c4o+2];
        S->sraw[head][c4o+3] = a0.w + Bp[c4o+3];
      }
    }
    // ---- nov/relax (2 warps) ----
    if (tid < 64){
      int rel = wid;
      const float* vw = rel ? relax_w : nov_w;
      float s = 0.f;
      #pragma unroll
      for (int k = 0; k < 4; k++){ int i = lane + k*32; s += S->sct[i] * vw[i]; }
      s = rsum32(s);
      if (lane == 0){
        float r = sigm(s + (rel ? relax_b[0] : nov_b[0])) * S->sval;
        if (rel) S->srl = r; else S->snv = r;
      }
    }

    // ---- cc_w [128,2048]: unroll 16 ----
    u64 A0[2] = {0,0};
    {
      const ulonglong2* W = (const ulonglong2*)cc_w;
      #pragma unroll 16
      for (int i = 0; i < 128; i++){
        ulonglong2 wv = W[i*512 + tid];
        u64 p0 = pack2(S->sct[i]);
        fma2(A0[0], p0, wv.x); fma2(A0[1], p0, wv.y);
      }
    }

    // ---- att_w [128,128] ----
    {
      u64 ax = 0, ay = 0;
      const int lo = isl * 8;
      #pragma unroll
      for (int r = 0; r < 8; r++){
        const int i = lo + r;
        ulonglong2 w = *(const ulonglong2*)&att_w[i*128 + j4*4];
        u64 p0 = pack2(S->sct[i]);
        fma2(ax, p0, w.x); fma2(ay, p0, w.y);
      }
      float2 l = unpack2(ax), h2 = unpack2(ay);
      *(float4*)&S->sbuf[isl][j4*4] = make_float4(l.x, l.y, h2.x, h2.y);
    }
    __syncthreads(); // S7
    if (tid < 128){
      float s = att_b[tid];
      #pragma unroll
      for (int k = 0; k < 16; k++) s += S->sbuf[k][tid];
      S->satt[tid] = s;
    }
    if (wid == 8){
      const int c = lane & 15;
      float graw = S->sraw[0][c];
      float araw = S->sraw[1][c];
      float mx = rmax16(araw);
      float ex = expf(araw - mx);
      float sm = rsum16(ex);
      float assign = ex / sm;
      float gate = sigm(graw) * S->sval;
      float ss = gate * assign;
      S->sgs[c] = ss;
      float cs = splus(S->sraw[2][c]) + EPSF;
      float md = tanhf(S->sraw[3][c]);
      float sp = S->ssp[c]; sp += ss*(cs - sp); S->ssp[c] = sp;
      float m  = S->smaM[c]; m += ss*md;        S->smaM[c] = m;
    }
    __syncthreads(); // S8

    // ---- center update ----
    {
      const int ccC = tid >> 5, ccH = tid & 31;
      float4 bv = *(const float4*)&cc_b[ccC*128 + ccH*4];
      float4 at = *(const float4*)&S->satt[ccH*4];
      float2 l  = unpack2(A0[0]);
      float2 hh = unpack2(A0[1]);
      float4 cand = make_float4(l.x+bv.x, l.y+bv.y, hh.x+bv.z, hh.y+bv.w);
      float ssv = S->sgs[ccC];
      float nv  = 0.1f * S->snv;
      float4 v  = *(float4*)&S->sc[ccC][ccH*4];
      v.x += ssv*(cand.x - v.x); v.x += nv*(at.x - v.x);
      v.y += ssv*(cand.y - v.y); v.y += nv*(at.y - v.y);
      v.z += ssv*(cand.z - v.z); v.z += nv*(at.z - v.z);
      v.w += ssv*(cand.w - v.w); v.w += nv*(at.w - v.w);
      *(float4*)&S->sc[ccC][ccH*4] = v;
    }
    __syncthreads(); // S9

    // ---- Gram ----
    if (tid < 256){
      const int ii = tid >> 4, jj = tid & 15;
      const float4* Aa = (const float4*)S->sc[ii];
      const float4* Bv = (const float4*)S->sc[jj];
      float d0=0.f, d1=0.f, d2s=0.f, d3=0.f;
      #pragma unroll 8
      for (int k = 0; k < 32; k++){
        float4 a4 = Aa[k], b4 = Bv[k];
        d0 += a4.x*b4.x; d1 += a4.y*b4.y; d2s += a4.z*b4.z; d3 += a4.w*b4.w;
      }
      float dot = (d0+d1) + (d2s+d3);
      S->smix[ii][jj] = dot;
      if (ii == jj) S->ssq[ii] = dot;
    }
    __syncthreads(); // S10
    if (tid < 256){
      const int row = (tid>>5)*2 + (lane >> 4);
      const int jj  = lane & 15;
      float Gij = S->smix[row][jj];
      float d2v = fmaxf(S->ssq[row] + S->ssq[jj] - 2.f*Gij, 0.f);
      float comp = -d2v / (S->ssp[row] + S->ssp[jj] + EPSF) + S->smaM[jj];
      float mx = rmax16(comp);
      float ex = expf(comp - mx);
      float sm = rsum16(ex);
      float mix = ex / sm;
      S->smix[row][jj] = mix;
      float msp = rsum16(mix * S->ssp[jj]);
      float mms = rsum16(mix * S->smaM[jj]);
      if ((lane & 15) == 0){ S->sms[row] = msp; S->smm[row] = mms; }
    }
    __syncthreads(); // S11
    {
      const int igrp = tid >> 7;
      float cr[16];
      #pragma unroll
      for (int c = 0; c < 16; c++) cr[c] = S->sc[c][ht];
      float rl = S->srl;
      float res[4];
      #pragma unroll
      for (int q = 0; q < 4; q++){
        const int i = igrp*4 + q;
        const float4* mr = (const float4*)S->smix[i];
        float4 m0 = mr[0], m1 = mr[1], m2v = mr[2], m3 = mr[3];
        float mc = m0.x*cr[0]+m0.y*cr[1]+m0.z*cr[2]+m0.w*cr[3]
                 + m1.x*cr[4]+m1.y*cr[5]+m1.z*cr[6]+m1.w*cr[7]
                 + m2v.x*cr[8]+m2v.y*cr[9]+m2v.z*cr[10]+m2v.w*cr[11]
                 + m3.x*cr[12]+m3.y*cr[13]+m3.z*cr[14]+m3.w*cr[15];
        res[q] = (1.f-rl)*cr[i] + rl*mc;
      }
      __syncthreads(); // S11b
      #pragma unroll
      for (int q = 0; q < 4; q++) S->sc[igrp*4 + q][ht] = res[q];
    }
    if (wid == 8){
      const int c = lane & 15;
      float rl2 = S->srl;
      float sp = S->ssp[c];
      float m  = S->smaM[c];
      float sp2 = (1.f-rl2)*sp + rl2*S->sms[c];
      float m2  = (1.f-rl2)*m  + rl2*S->smm[c];
      float score = m2 + logf(1.f/(sp2+EPSF)+EPSF);
      float mx = rmax16(score);
      float ex = expf(score - mx);
      float sm = rsum16(ex);
      float ca = ex / sm;
      S->ssp[c] = sp2*(1.f - 0.05f*ca*S->sval) + EPSF;
      S->smaM[c] = m2;
    }
    __syncthreads(); // S12
    tok_cur = tok_nxt; e_cur = e_nxt;
  }

  // ---- epilogue ----
  if (wid == 8){
    const int c = lane & 15;
    float sp = S->ssp[c];
    float m  = S->smaM[c];
    float score = m + logf(1.f/(sp+EPSF)+EPSF);
    float mx = rmax16(score);
    float ex = expf(score - mx);
    float sm = rsum16(ex);
    float a  = ex / sm;
    S->sal[c] = a;
    float u   = rsum16(a*sp);
    float ent = rsum16(-a*logf(fmaxf(a,1e-8f)));
    float mm2 = rmax16(m);
    float en  = mm2 + logf(rsum16(expf(m - mm2)));
    float bv = a;
    int   bi = c;
    #pragma unroll
    for (int o = 8; o; o >>= 1){
      float ov = __shfl_xor_sync(0xffffffffu, bv, o);
      int   oi = __shfl_xor_sync(0xffffffffu, bi, o);
      if (ov > bv || (ov == bv && oi < bi)){ bv = ov; bi = oi; }
    }
    if (lane == 0){
      S->sci[256] = u; S->sci[258] = en; S->sci[259] = ent; S->sidx = bi;
    }
  }
  __syncthreads();
  if (tid < 128){
    float core = 0.f;
    #pragma unroll
    for (int c = 0; c < 16; c++) core += S->sal[c] * S->sc[c][tid];
    float dv = 0.f;
    #pragma unroll
    for (int c = 0; c < 16; c++){ float dd = S->sc[c][tid] - core; dv += S->sal[c]*dd*dd; }
    dv = rsum32(dv);
    if (lane == 0) S->sred[wid][2] = dv;
    float strong = S->sc[S->sidx][tid];
    S->sci[tid] = core;
    S->sci[128+tid] = strong;
  }
  __syncthreads();
  if (tid == 0)
    S->sci[257] = (S->sred[0][2]+S->sred[1][2]+S->sred[2][2]+S->sred[3][2]) * (1.f/128.f);
  __syncthreads();
  {
    u64 ax = 0, ay = 0;
    const int lo = isl * 16;
    #pragma unroll
    for (int r = 0; r < 16; r++){
      const int i = lo + r;
      ulonglong2 w = *(const ulonglong2*)&cw1[i*128 + j4*4];
      u64 p0 = pack2(S->sci[i]);
      fma2(ax, p0, w.x); fma2(ay, p0, w.y);
    }
    if (isl < 4){
      const int i = 256 + isl;
      ulonglong2 w = *(const ulonglong2*)&cw1[i*128 + j4*4];
      u64 p0 = pack2(S->sci[i]);
      fma2(ax, p0, w.x); fma2(ay, p0, w.y);
    }
    float2 l = unpack2(ax), h2 = unpack2(ay);
    *(float4*)&S->sbuf[isl][j4*4] = make_float4(l.x, l.y, h2.x, h2.y);
  }
  __syncthreads();
  if (tid < 128){
    float s = cb1[tid];
    #pragma unroll
    for (int k = 0; k < 16; k++) s += S->sbuf[k][tid];
    S->sh1[tid] = 0.5f * s * (1.f + erff(s * 0.70710678118654752440f));
  }
  __syncthreads();
  if (tid < 8){
    float s = cb2[tid];
    #pragma unroll 4
    for (int i = 0; i < 128; i++) s += S->sh1[i] * cw2[i*8 + tid];
    out[b*8 + tid] = s;
  }
}

extern "C" void kernel_launch(void* const* d_in, const int* in_sizes, int n_in,
                              void* d_out, int out_size){
  (void)in_sizes; (void)n_in; (void)out_size;
  cudaFuncSetAttribute(cfrm_kernel, cudaFuncAttributeMaxDynamicSharedMemorySize, (int)sizeof(Smem));
  cfrm_kernel<<<128, 512, sizeof(Smem)>>>(
    (const int*)  d_in[0],  (const float*)d_in[1],  (const float*)d_in[2],  (const float*)d_in[3],
    (const float*)d_in[4],  (const float*)d_in[5],  (const float*)d_in[6],  (const float*)d_in[7],
    (const float*)d_in[8],  (const float*)d_in[9],  (const float*)d_in[10], (const float*)d_in[11],
    (const float*)d_in[12], (const float*)d_in[13], (const float*)d_in[14], (const float*)d_in[15],
    (const float*)d_in[16], (const float*)d_in[17], (const float*)d_in[18], (const float*)d_in[19],
    (const float*)d_in[20], (const float*)d_in[21], (const float*)d_in[22], (const float*)d_in[23],
    (const float*)d_in[24], (const float*)d_in[25], (const float*)d_in[26], (const float*)d_in[27],
    (float*)d_out);
}